// round 1
// baseline (speedup 1.0000x reference)
#include <cuda_runtime.h>
#include <math.h>

// Problem constants
#define Bn   16
#define Cc   256
#define Nn   4096
#define Hh   4
#define Dd   64
#define O3   768     // 3 * Hh * Dd
#define HID  256     // Hh * Dd
#define SCALE 0.125f // 64^-0.5

// Scratch (device globals; allocation inside kernel_launch is forbidden)
__device__ float g_qkv[(size_t)Bn * O3 * Nn];   // 192 MB: qkv projection, softmaxed in place
__device__ float g_ctx[(size_t)Bn * Hh * Dd * Dd]; // 1 MB:  context[d][e] per (b,h)
__device__ float g_att[(size_t)Bn * HID * Nn];  // 64 MB: attention output before out-proj

// ---------------------------------------------------------------------------
// Generic tiled SGEMM: C[m,n] = sum_k A[m,k] * B[k,n] (+ bias[m])
// BM=BN=64, BK=16, 256 threads, 4x4 per thread. Batched via blockIdx.z.
// ---------------------------------------------------------------------------
__global__ void gemm64(const float* __restrict__ A,
                       const float* __restrict__ B0, size_t bStride,
                       float* __restrict__ C0, size_t cStride,
                       const float* __restrict__ bias,
                       int M, int N, int K)
{
    const float* Bm = B0 + (size_t)blockIdx.z * bStride;
    float*       Cm = C0 + (size_t)blockIdx.z * cStride;

    __shared__ float As[64][17];  // [m][k], padded
    __shared__ float Bs[16][65];  // [k][n], padded

    const int tid = threadIdx.x;
    const int ty  = tid >> 4;    // 0..15 (m direction)
    const int tx  = tid & 15;    // 0..15 (n direction)
    const int mBlk = blockIdx.y * 64;
    const int nBlk = blockIdx.x * 64;

    float acc[4][4];
    #pragma unroll
    for (int i = 0; i < 4; i++)
        #pragma unroll
        for (int j = 0; j < 4; j++) acc[i][j] = 0.f;

    for (int kk = 0; kk < K; kk += 16) {
        // Load A tile 64x16
        #pragma unroll
        for (int i = 0; i < 4; i++) {
            int idx = tid + i * 256;
            int m = idx >> 4, k = idx & 15;
            As[m][k] = A[(size_t)(mBlk + m) * K + kk + k];
        }
        // Load B tile 16x64 (coalesced over n)
        #pragma unroll
        for (int i = 0; i < 4; i++) {
            int idx = tid + i * 256;
            int k = idx >> 6, n = idx & 63;
            Bs[k][n] = Bm[(size_t)(kk + k) * N + nBlk + n];
        }
        __syncthreads();

        #pragma unroll
        for (int k = 0; k < 16; k++) {
            float a[4], b[4];
            #pragma unroll
            for (int i = 0; i < 4; i++) a[i] = As[ty * 4 + i][k];
            #pragma unroll
            for (int j = 0; j < 4; j++) b[j] = Bs[k][tx * 4 + j];
            #pragma unroll
            for (int i = 0; i < 4; i++)
                #pragma unroll
                for (int j = 0; j < 4; j++)
                    acc[i][j] = fmaf(a[i], b[j], acc[i][j]);
        }
        __syncthreads();
    }

    #pragma unroll
    for (int i = 0; i < 4; i++) {
        int m = mBlk + ty * 4 + i;
        float bv = bias ? bias[m] : 0.f;
        #pragma unroll
        for (int j = 0; j < 4; j++) {
            Cm[(size_t)m * N + nBlk + tx * 4 + j] = acc[i][j] + bv;
        }
    }
}

// ---------------------------------------------------------------------------
// Softmax over d (q section of g_qkv), times SCALE. One thread per (b,h,n).
// ---------------------------------------------------------------------------
__global__ void softmax_q_kernel()
{
    int idx = blockIdx.x * blockDim.x + threadIdx.x;  // over Bn*Hh*Nn = 262144
    if (idx >= Bn * Hh * Nn) return;
    int n = idx & (Nn - 1);
    int h = (idx >> 12) & (Hh - 1);
    int b = idx >> 14;

    float* base = g_qkv + ((size_t)b * O3 + h * Dd) * Nn + n;

    float vals[Dd];
    float mx = -INFINITY;
    #pragma unroll
    for (int d = 0; d < Dd; d++) {
        vals[d] = base[(size_t)d * Nn];
        mx = fmaxf(mx, vals[d]);
    }
    float s = 0.f;
    #pragma unroll
    for (int d = 0; d < Dd; d++) {
        vals[d] = expf(vals[d] - mx);
        s += vals[d];
    }
    float inv = SCALE / s;
    #pragma unroll
    for (int d = 0; d < Dd; d++)
        base[(size_t)d * Nn] = vals[d] * inv;
}

// ---------------------------------------------------------------------------
// Softmax over n (k section of g_qkv). One block (256 thr) per (b,h,d) row.
// ---------------------------------------------------------------------------
__global__ void softmax_k_kernel()
{
    int row = blockIdx.x;              // Bn*Hh*Dd = 4096 rows
    int b   = row >> 8;                // Hh*Dd = 256 rows per batch
    int hd  = row & 255;
    float* base = g_qkv + ((size_t)b * O3 + HID + hd) * Nn;

    __shared__ float red[256];
    const int tid = threadIdx.x;

    float v[16];
    float mx = -INFINITY;
    #pragma unroll
    for (int i = 0; i < 16; i++) {
        v[i] = base[tid + i * 256];
        mx = fmaxf(mx, v[i]);
    }
    red[tid] = mx;
    __syncthreads();
    for (int s = 128; s > 0; s >>= 1) {
        if (tid < s) red[tid] = fmaxf(red[tid], red[tid + s]);
        __syncthreads();
    }
    mx = red[0];
    __syncthreads();

    float sum = 0.f;
    #pragma unroll
    for (int i = 0; i < 16; i++) {
        v[i] = expf(v[i] - mx);
        sum += v[i];
    }
    red[tid] = sum;
    __syncthreads();
    for (int s = 128; s > 0; s >>= 1) {
        if (tid < s) red[tid] += red[tid + s];
        __syncthreads();
    }
    float inv = 1.f / red[0];

    #pragma unroll
    for (int i = 0; i < 16; i++)
        base[tid + i * 256] = v[i] * inv;
}

// ---------------------------------------------------------------------------
// context[b,h,d,e] = sum_n k[d,n] * v[e,n].  One block per (b,h), 256 thr.
// ---------------------------------------------------------------------------
__global__ void context_kernel()
{
    int bh = blockIdx.x;               // 64
    int b = bh >> 2, h = bh & 3;
    const float* Kp = g_qkv + ((size_t)b * O3 + HID     + h * Dd) * Nn;
    const float* Vp = g_qkv + ((size_t)b * O3 + 2 * HID + h * Dd) * Nn;

    __shared__ float Ks[64][65];
    __shared__ float Vs[64][65];

    const int tid = threadIdx.x;
    const int ty = tid >> 4, tx = tid & 15;

    float acc[4][4];
    #pragma unroll
    for (int i = 0; i < 4; i++)
        #pragma unroll
        for (int j = 0; j < 4; j++) acc[i][j] = 0.f;

    for (int nn = 0; nn < Nn; nn += 64) {
        #pragma unroll
        for (int i = 0; i < 16; i++) {
            int idx = tid + i * 256;
            int r = idx >> 6, c = idx & 63;
            Ks[r][c] = Kp[(size_t)r * Nn + nn + c];
            Vs[r][c] = Vp[(size_t)r * Nn + nn + c];
        }
        __syncthreads();
        #pragma unroll
        for (int n2 = 0; n2 < 64; n2++) {
            float a[4], v[4];
            #pragma unroll
            for (int i = 0; i < 4; i++) a[i] = Ks[ty * 4 + i][n2];
            #pragma unroll
            for (int j = 0; j < 4; j++) v[j] = Vs[tx * 4 + j][n2];
            #pragma unroll
            for (int i = 0; i < 4; i++)
                #pragma unroll
                for (int j = 0; j < 4; j++)
                    acc[i][j] = fmaf(a[i], v[j], acc[i][j]);
        }
        __syncthreads();
    }

    #pragma unroll
    for (int i = 0; i < 4; i++)
        #pragma unroll
        for (int j = 0; j < 4; j++)
            g_ctx[((size_t)bh * Dd + ty * 4 + i) * Dd + tx * 4 + j] = acc[i][j];
}

// ---------------------------------------------------------------------------
// att[b, h*64+e, n] = sum_d ctx[b,h,d,e] * q[b,h,d,n]
// Grid: (Nn/64, Bn*Hh), 256 threads. Each thread: one n, 16 e values.
// ---------------------------------------------------------------------------
__global__ void apply_ctx_kernel()
{
    int bh = blockIdx.y;
    int b = bh >> 2, h = bh & 3;
    int n0 = blockIdx.x * 64;

    const float* Qp  = g_qkv + ((size_t)b * O3 + h * Dd) * Nn;
    const float* ctx = g_ctx + (size_t)bh * Dd * Dd;  // [d][e]

    __shared__ float Qs[64][65];
    __shared__ float Cs[64][64];

    const int tid = threadIdx.x;
    // load ctx (4096 floats) and q tile (64x64)
    #pragma unroll
    for (int i = 0; i < 16; i++) {
        int idx = tid + i * 256;
        Cs[idx >> 6][idx & 63] = ctx[idx];
        int r = idx >> 6, c = idx & 63;
        Qs[r][c] = Qp[(size_t)r * Nn + n0 + c];
    }
    __syncthreads();

    const int tx = tid & 63;       // local n
    const int ey = tid >> 6;       // 0..3 -> e block of 16
    float out[16];
    #pragma unroll
    for (int j = 0; j < 16; j++) out[j] = 0.f;

    #pragma unroll
    for (int d = 0; d < 64; d++) {
        float q = Qs[d][tx];
        #pragma unroll
        for (int j = 0; j < 16; j++)
            out[j] = fmaf(Cs[d][ey * 16 + j], q, out[j]);
    }

    #pragma unroll
    for (int j = 0; j < 16; j++) {
        int e = ey * 16 + j;
        g_att[((size_t)b * HID + h * Dd + e) * Nn + n0 + tx] = out[j];
    }
}

// ---------------------------------------------------------------------------
extern "C" void kernel_launch(void* const* d_in, const int* in_sizes, int n_in,
                              void* d_out, int out_size)
{
    const float* x     = (const float*)d_in[0];  // (16,256,64,64)
    const float* w_qkv = (const float*)d_in[1];  // (768,256)
    const float* w_out = (const float*)d_in[2];  // (256,256)
    const float* b_out = (const float*)d_in[3];  // (256,)
    float* out = (float*)d_out;                  // (16,256,64,64)

    float* qkv; cudaGetSymbolAddress((void**)&qkv, g_qkv);
    float* att; cudaGetSymbolAddress((void**)&att, g_att);

    // 1) QKV projection: per batch, [768,256] x [256,4096]
    {
        dim3 grid(Nn / 64, O3 / 64, Bn);
        gemm64<<<grid, 256>>>(w_qkv, x, (size_t)Cc * Nn,
                              qkv, (size_t)O3 * Nn, nullptr,
                              O3, Nn, Cc);
    }

    // 2) softmax over d on q (scaled), softmax over n on k
    softmax_q_kernel<<<(Bn * Hh * Nn) / 256, 256>>>();
    softmax_k_kernel<<<Bn * Hh * Dd, 256>>>();

    // 3) context = k @ v^T per (b,h)
    context_kernel<<<Bn * Hh, 256>>>();

    // 4) att = ctx^T @ q per (b,h)
    {
        dim3 grid(Nn / 64, Bn * Hh);
        apply_ctx_kernel<<<grid, 256>>>();
    }

    // 5) output projection + bias: per batch, [256,256] x [256,4096]
    {
        dim3 grid(Nn / 64, HID / 64, Bn);
        gemm64<<<grid, 256>>>(w_out, att, (size_t)HID * Nn,
                              out, (size_t)HID * Nn, b_out,
                              HID, Nn, Cc);
    }
}

// round 3
// speedup vs baseline: 2.0435x; 2.0435x over previous
#include <cuda_runtime.h>
#include <math.h>
#include <stdint.h>

// Problem constants
#define Bn   16
#define Cc   256
#define Nn   4096
#define Hh   4
#define Dd   64
#define O3   768
#define HID  256
#define SCALE 0.125f

// Scratch
__device__ float g_qkv[(size_t)Bn * O3 * Nn];                 // 192 MB
__device__ float g_ctxp[(size_t)Bn * Hh * 8 * Dd * Dd];       // 8 MB
__device__ float g_w2[(size_t)Bn * HID * HID];                // 4 MB

// ===========================================================================
// 3xTF32 helpers (baseline PTX, legal on sm_103 non-'a')
// ===========================================================================
__device__ __forceinline__ void split_tf32(float x, float& hi, float& lo) {
    uint32_t u;
    asm("cvt.rna.tf32.f32 %0, %1;" : "=r"(u) : "f"(x));
    hi = __uint_as_float(u);
    float r = x - hi;
    asm("cvt.rna.tf32.f32 %0, %1;" : "=r"(u) : "f"(r));
    lo = __uint_as_float(u);
}

__device__ __forceinline__ void mma8(float* d, const uint32_t* a, const uint32_t* b) {
    asm volatile(
        "mma.sync.aligned.m16n8k8.row.col.f32.tf32.tf32.f32 "
        "{%0,%1,%2,%3},{%4,%5,%6,%7},{%8,%9},{%0,%1,%2,%3};"
        : "+f"(d[0]), "+f"(d[1]), "+f"(d[2]), "+f"(d[3])
        : "r"(a[0]), "r"(a[1]), "r"(a[2]), "r"(a[3]), "r"(b[0]), "r"(b[1]));
}

// ===========================================================================
// Tensor-core GEMM (3xTF32 via mma.sync): C[m,n] = sum_k A[m,k]*B[k,n] (+bias)
// Block 128x128, K=256 in 8 slices of 32, double-buffered smem.
// 8 warps = 2(m) x 4(n); warp tile 64x32; mma m16n8k8.
// A: row-major [M x 256]. B: [256 x Nn] (n contiguous).
// ===========================================================================
#define PA 36           // A smem pitch (floats), [m][PA]
#define PB 136          // B smem pitch (floats), [k][PB]
#define ASZ (128 * PA)  // 4608 floats
#define BSZ (32 * PB)   // 4352 floats
#define STAGEF (2 * ASZ + 2 * BSZ)              // floats per stage (hi+lo A, hi+lo B)
#define GT_SMEM_BYTES (2 * STAGEF * 4)          // 143360

__global__ void __launch_bounds__(256, 1)
gemm_tc(const float* __restrict__ A, size_t aStride,
        const float* __restrict__ B, size_t bStride,
        float* __restrict__ C, size_t cStride,
        const float* __restrict__ bias)
{
    extern __shared__ float smf[];
    const int tid  = threadIdx.x;
    const int wid  = tid >> 5;
    const int lane = tid & 31;
    const int wm   = (wid >> 2) * 64;   // warp m offset in tile
    const int wn   = (wid & 3) * 32;    // warp n offset in tile
    const int mBlk = blockIdx.y * 128;
    const int nBlk = blockIdx.x * 128;

    const float* Ag = A + (size_t)blockIdx.z * aStride + (size_t)mBlk * Cc;
    const float* Bg = B + (size_t)blockIdx.z * bStride + nBlk;
    float*       Cg = C + (size_t)blockIdx.z * cStride;

    float acc[4][4][4];
    #pragma unroll
    for (int i = 0; i < 4; i++)
        #pragma unroll
        for (int j = 0; j < 4; j++)
            #pragma unroll
            for (int r = 0; r < 4; r++) acc[i][j][r] = 0.f;

    float4 pa[4], pb[4];

    // global loads for slice s into registers (fully coalesced)
    auto loadG = [&](int s) {
        const int kk = s * 32;
        #pragma unroll
        for (int p = 0; p < 4; p++) {
            int id = tid + p * 256;
            int m  = id >> 3, kq = id & 7;            // A: 128 rows x 8 float4
            pa[p] = *(const float4*)(Ag + (size_t)m * Cc + kk + kq * 4);
            int kb = id >> 5, nq = id & 31;           // B: 32 rows x 32 float4
            pb[p] = *(const float4*)(Bg + (size_t)(kk + kb) * Nn + nq * 4);
        }
    };

    // split + store registers into smem stage buf
    auto storeS = [&](int buf) {
        float* aH = smf + buf * STAGEF;
        float* aL = aH + ASZ;
        float* bH = aL + ASZ;
        float* bL = bH + BSZ;
        #pragma unroll
        for (int p = 0; p < 4; p++) {
            int id = tid + p * 256;
            int m  = id >> 3, kq = id & 7;
            const float* av = (const float*)&pa[p];
            #pragma unroll
            for (int j = 0; j < 4; j++) {
                float h, l; split_tf32(av[j], h, l);
                aH[m * PA + kq * 4 + j] = h;
                aL[m * PA + kq * 4 + j] = l;
            }
            int kb = id >> 5, nq = id & 31;
            const float* bv = (const float*)&pb[p];
            #pragma unroll
            for (int j = 0; j < 4; j++) {
                float h, l; split_tf32(bv[j], h, l);
                bH[kb * PB + nq * 4 + j] = h;
                bL[kb * PB + nq * 4 + j] = l;
            }
        }
    };

    // compute one 32-k slice from stage buf
    auto compute = [&](int buf) {
        const float* aH = smf + buf * STAGEF;
        const float* aL = aH + ASZ;
        const float* bH = aL + ASZ;
        const float* bL = bH + BSZ;
        #pragma unroll
        for (int ks = 0; ks < 4; ks++) {
            const int k0 = ks * 8 + (lane & 3);
            uint32_t bh[4][2], bl[4][2];
            #pragma unroll
            for (int fn = 0; fn < 4; fn++) {
                int cn = wn + fn * 8 + (lane >> 2);
                bh[fn][0] = __float_as_uint(bH[k0 * PB + cn]);
                bh[fn][1] = __float_as_uint(bH[(k0 + 4) * PB + cn]);
                bl[fn][0] = __float_as_uint(bL[k0 * PB + cn]);
                bl[fn][1] = __float_as_uint(bL[(k0 + 4) * PB + cn]);
            }
            #pragma unroll
            for (int fm = 0; fm < 4; fm++) {
                int row = wm + fm * 16 + (lane >> 2);
                int col = ks * 8 + (lane & 3);
                uint32_t ah[4], al[4];
                ah[0] = __float_as_uint(aH[row * PA + col]);
                ah[1] = __float_as_uint(aH[(row + 8) * PA + col]);
                ah[2] = __float_as_uint(aH[row * PA + col + 4]);
                ah[3] = __float_as_uint(aH[(row + 8) * PA + col + 4]);
                al[0] = __float_as_uint(aL[row * PA + col]);
                al[1] = __float_as_uint(aL[(row + 8) * PA + col]);
                al[2] = __float_as_uint(aL[row * PA + col + 4]);
                al[3] = __float_as_uint(aL[(row + 8) * PA + col + 4]);
                #pragma unroll
                for (int fn = 0; fn < 4; fn++) {
                    mma8(acc[fm][fn], ah, bh[fn]);
                    mma8(acc[fm][fn], ah, bl[fn]);
                    mma8(acc[fm][fn], al, bh[fn]);
                }
            }
        }
    };

    // pipeline: prefetch next slice while computing current
    loadG(0);
    storeS(0);
    __syncthreads();
    #pragma unroll 1
    for (int s = 0; s < 8; s++) {
        if (s < 7) loadG(s + 1);
        compute(s & 1);
        if (s < 7) {
            __syncthreads();      // everyone done reading buf (s+1)&1 from iter s-1
            storeS((s + 1) & 1);
            __syncthreads();
        }
    }

    // epilogue: direct stores (32B-sector friendly: 8 consecutive bytes x2 per thread pair)
    #pragma unroll
    for (int fm = 0; fm < 4; fm++) {
        int row = mBlk + wm + fm * 16 + (lane >> 2);
        float b0 = bias ? bias[row]     : 0.f;
        float b8 = bias ? bias[row + 8] : 0.f;
        #pragma unroll
        for (int fn = 0; fn < 4; fn++) {
            int col = nBlk + wn + fn * 8 + (lane & 3) * 2;
            float2 v0 = { acc[fm][fn][0] + b0, acc[fm][fn][1] + b0 };
            float2 v1 = { acc[fm][fn][2] + b8, acc[fm][fn][3] + b8 };
            *(float2*)&Cg[(size_t)row * Nn + col]       = v0;
            *(float2*)&Cg[(size_t)(row + 8) * Nn + col] = v1;
        }
    }
}

// ===========================================================================
// Softmax over d on q (x SCALE). One thread per (b,h,n).
// ===========================================================================
__global__ void softmax_q_kernel()
{
    int idx = blockIdx.x * blockDim.x + threadIdx.x;
    if (idx >= Bn * Hh * Nn) return;
    int n = idx & (Nn - 1);
    int h = (idx >> 12) & (Hh - 1);
    int b = idx >> 14;
    float* base = g_qkv + ((size_t)b * O3 + h * Dd) * Nn + n;

    float vals[Dd];
    float mx = -INFINITY;
    #pragma unroll
    for (int d = 0; d < Dd; d++) { vals[d] = base[(size_t)d * Nn]; mx = fmaxf(mx, vals[d]); }
    float s = 0.f;
    #pragma unroll
    for (int d = 0; d < Dd; d++) { vals[d] = expf(vals[d] - mx); s += vals[d]; }
    float inv = SCALE / s;
    #pragma unroll
    for (int d = 0; d < Dd; d++) base[(size_t)d * Nn] = vals[d] * inv;
}

// ===========================================================================
// Softmax over n on k. One block per (b,h,d) row.
// ===========================================================================
__global__ void softmax_k_kernel()
{
    int row = blockIdx.x;
    int b = row >> 8;
    int hd = row & 255;
    float* base = g_qkv + ((size_t)b * O3 + HID + hd) * Nn;

    __shared__ float red[256];
    const int tid = threadIdx.x;
    float v[16];
    float mx = -INFINITY;
    #pragma unroll
    for (int i = 0; i < 16; i++) { v[i] = base[tid + i * 256]; mx = fmaxf(mx, v[i]); }
    red[tid] = mx; __syncthreads();
    for (int s = 128; s > 0; s >>= 1) { if (tid < s) red[tid] = fmaxf(red[tid], red[tid + s]); __syncthreads(); }
    mx = red[0]; __syncthreads();
    float sum = 0.f;
    #pragma unroll
    for (int i = 0; i < 16; i++) { v[i] = expf(v[i] - mx); sum += v[i]; }
    red[tid] = sum; __syncthreads();
    for (int s = 128; s > 0; s >>= 1) { if (tid < s) red[tid] += red[tid + s]; __syncthreads(); }
    float inv = 1.f / red[0];
    #pragma unroll
    for (int i = 0; i < 16; i++) base[tid + i * 256] = v[i] * inv;
}

// ===========================================================================
// Context partials: ctxp[bh][p][d][e] = sum_{n in chunk p} k_sm[d,n]*v[e,n]
// ===========================================================================
__global__ void context_part()
{
    int bh = blockIdx.x;
    int p  = blockIdx.y;
    int b = bh >> 2, h = bh & 3;
    const float* Kp = g_qkv + ((size_t)b * O3 + HID     + h * Dd) * Nn;
    const float* Vp = g_qkv + ((size_t)b * O3 + 2 * HID + h * Dd) * Nn;

    __shared__ float Ks[64][65];
    __shared__ float Vs[64][65];
    const int tid = threadIdx.x;
    const int ty = tid >> 4, tx = tid & 15;

    float acc[4][4];
    #pragma unroll
    for (int i = 0; i < 4; i++)
        #pragma unroll
        for (int j = 0; j < 4; j++) acc[i][j] = 0.f;

    for (int nn = p * 512; nn < p * 512 + 512; nn += 64) {
        #pragma unroll
        for (int i = 0; i < 16; i++) {
            int idx = tid + i * 256;
            int r = idx >> 6, c = idx & 63;
            Ks[r][c] = Kp[(size_t)r * Nn + nn + c];
            Vs[r][c] = Vp[(size_t)r * Nn + nn + c];
        }
        __syncthreads();
        #pragma unroll
        for (int n2 = 0; n2 < 64; n2++) {
            float a[4], v[4];
            #pragma unroll
            for (int i = 0; i < 4; i++) a[i] = Ks[ty * 4 + i][n2];
            #pragma unroll
            for (int j = 0; j < 4; j++) v[j] = Vs[tx * 4 + j][n2];
            #pragma unroll
            for (int i = 0; i < 4; i++)
                #pragma unroll
                for (int j = 0; j < 4; j++)
                    acc[i][j] = fmaf(a[i], v[j], acc[i][j]);
        }
        __syncthreads();
    }

    float* dst = g_ctxp + ((size_t)bh * 8 + p) * (Dd * Dd);
    #pragma unroll
    for (int i = 0; i < 4; i++)
        #pragma unroll
        for (int j = 0; j < 4; j++)
            dst[(ty * 4 + i) * Dd + tx * 4 + j] = acc[i][j];
}

// ===========================================================================
// W2[b][c][h*64+d] = sum_e w_out[c][h*64+e] * ctx[bh][d][e]
// ===========================================================================
__global__ void w2_kernel(const float* __restrict__ w_out)
{
    int bh = blockIdx.x;
    int b = bh >> 2, h = bh & 3;
    __shared__ float ctx[Dd * Dd];
    const int tid = threadIdx.x;

    for (int i = tid; i < Dd * Dd; i += 256) {
        float s = 0.f;
        #pragma unroll
        for (int p = 0; p < 8; p++)
            s += g_ctxp[((size_t)bh * 8 + p) * (Dd * Dd) + i];
        ctx[i] = s;
    }
    __syncthreads();

    int c = tid;
    float w[Dd];
    #pragma unroll
    for (int e = 0; e < Dd; e++) w[e] = w_out[c * HID + h * Dd + e];
    #pragma unroll 4
    for (int d = 0; d < Dd; d++) {
        float s = 0.f;
        #pragma unroll
        for (int e = 0; e < Dd; e++) s = fmaf(w[e], ctx[d * Dd + e], s);
        g_w2[((size_t)b * HID + c) * HID + h * Dd + d] = s;
    }
}

// ===========================================================================
extern "C" void kernel_launch(void* const* d_in, const int* in_sizes, int n_in,
                              void* d_out, int out_size)
{
    const float* x     = (const float*)d_in[0];
    const float* w_qkv = (const float*)d_in[1];
    const float* w_out = (const float*)d_in[2];
    const float* b_out = (const float*)d_in[3];
    float* out = (float*)d_out;

    float* qkv; cudaGetSymbolAddress((void**)&qkv, g_qkv);
    float* w2;  cudaGetSymbolAddress((void**)&w2, g_w2);

    static int attr_done = 0;
    if (!attr_done) {
        cudaFuncSetAttribute(gemm_tc, cudaFuncAttributeMaxDynamicSharedMemorySize, GT_SMEM_BYTES);
        attr_done = 1;
    }

    // 1) QKV projection: [768,256] x [256,4096] per batch (tensor cores)
    {
        dim3 grid(Nn / 128, O3 / 128, Bn);
        gemm_tc<<<grid, 256, GT_SMEM_BYTES>>>(w_qkv, 0,
                                              x, (size_t)Cc * Nn,
                                              qkv, (size_t)O3 * Nn, nullptr);
    }
    // 2) softmaxes
    softmax_q_kernel<<<(Bn * Hh * Nn) / 256, 256>>>();
    softmax_k_kernel<<<Bn * Hh * Dd, 256>>>();
    // 3) context partials over 8 n-chunks
    {
        dim3 grid(Bn * Hh, 8);
        context_part<<<grid, 256>>>();
    }
    // 4) W2 = w_out_h @ ctx_h^T (reduces partials)
    w2_kernel<<<Bn * Hh, 256>>>(w_out);
    // 5) out = W2_b @ q_sm_b + bias: [256,256] x [256,4096] per batch
    {
        dim3 grid(Nn / 128, HID / 128, Bn);
        gemm_tc<<<grid, 256, GT_SMEM_BYTES>>>(w2, (size_t)HID * HID,
                                              qkv, (size_t)O3 * Nn,
                                              out, (size_t)HID * Nn, b_out);
    }
}

// round 4
// speedup vs baseline: 3.2246x; 1.5780x over previous
#include <cuda_runtime.h>
#include <cuda_fp16.h>
#include <math.h>
#include <stdint.h>

// Problem constants
#define Bn   16
#define Cc   256
#define Nn   4096
#define Hh   4
#define Dd   64
#define O3   768
#define HID  256
#define SCALE 0.125f

// Scratch
__device__ float g_qkv[(size_t)Bn * O3 * Nn];                 // 192 MB
__device__ float g_ctxp[(size_t)Bn * Hh * 8 * Dd * Dd];       // 8 MB
__device__ float g_w2[(size_t)Bn * HID * HID];                // 4 MB

// ===========================================================================
// Helpers
// ===========================================================================
__device__ __forceinline__ uint32_t smem_u32(const void* p) {
    uint32_t a;
    asm("{ .reg .u64 t; cvta.to.shared.u64 t, %1; cvt.u32.u64 %0, t; }" : "=r"(a) : "l"(p));
    return a;
}

// 2-way fp16 split: x ~= hi + lo with ~22-24 bit combined mantissa
__device__ __forceinline__ void split_h(float x, __half& h, __half& l) {
    h = __float2half_rn(x);
    l = __float2half_rn(x - __half2float(h));
}

__device__ __forceinline__ void mma16(float* d, const uint32_t* a, const uint32_t* b) {
    asm volatile(
        "mma.sync.aligned.m16n8k16.row.col.f32.f16.f16.f32 "
        "{%0,%1,%2,%3},{%4,%5,%6,%7},{%8,%9},{%0,%1,%2,%3};"
        : "+f"(d[0]), "+f"(d[1]), "+f"(d[2]), "+f"(d[3])
        : "r"(a[0]), "r"(a[1]), "r"(a[2]), "r"(a[3]), "r"(b[0]), "r"(b[1]));
}

#define LDM_X4(r, addr) \
    asm volatile("ldmatrix.sync.aligned.m8n8.x4.shared.b16 {%0,%1,%2,%3}, [%4];" \
        : "=r"((r)[0]), "=r"((r)[1]), "=r"((r)[2]), "=r"((r)[3]) : "r"(addr))
#define LDM_X4_T(r, addr) \
    asm volatile("ldmatrix.sync.aligned.m8n8.x4.trans.shared.b16 {%0,%1,%2,%3}, [%4];" \
        : "=r"((r)[0]), "=r"((r)[1]), "=r"((r)[2]), "=r"((r)[3]) : "r"(addr))

// ===========================================================================
// GEMM (3-term FP16 split): C[m,n] = sum_k A[m,k]*B[k,n] (+bias)
// Block 128x128, K=256 in 8 slices of 32, double-buffered fp16 smem.
// 8 warps = 2(m) x 4(n); warp tile 64x32; mma m16n8k16 + ldmatrix.
// A: row-major [M x 256]. B: [256 x Nn] (n contiguous).
// ===========================================================================
#define PAH 40            // A smem pitch (fp16): conflict-free ldmatrix lines
#define PBH 136           // B smem pitch (fp16)
#define ASZH (128 * PAH)  // 5120 fp16
#define BSZH (32 * PBH)   // 4352 fp16
#define STAGEH (2 * ASZH + 2 * BSZH)      // 18944 fp16 per stage
#define GT_SMEM_BYTES (2 * STAGEH * 2)    // 75776 B

__global__ void __launch_bounds__(256, 1)
gemm_tc(const float* __restrict__ A, size_t aStride,
        const float* __restrict__ B, size_t bStride,
        float* __restrict__ C, size_t cStride,
        const float* __restrict__ bias)
{
    extern __shared__ __half smh[];
    const uint32_t sb = smem_u32(smh);
    const int tid  = threadIdx.x;
    const int wid  = tid >> 5;
    const int lane = tid & 31;
    const int wm   = (wid >> 2) * 64;
    const int wn   = (wid & 3) * 32;
    const int mBlk = blockIdx.y * 128;
    const int nBlk = blockIdx.x * 128;

    const float* Ag = A + (size_t)blockIdx.z * aStride + (size_t)mBlk * Cc;
    const float* Bg = B + (size_t)blockIdx.z * bStride + nBlk;
    float*       Cg = C + (size_t)blockIdx.z * cStride;

    float acc[4][4][4];
    #pragma unroll
    for (int i = 0; i < 4; i++)
        #pragma unroll
        for (int j = 0; j < 4; j++)
            #pragma unroll
            for (int r = 0; r < 4; r++) acc[i][j][r] = 0.f;

    float4 pa[4], pb[4];

    auto loadG = [&](int s) {
        const int kk = s * 32;
        #pragma unroll
        for (int p = 0; p < 4; p++) {
            int id = tid + p * 256;
            int m  = id >> 3, kq = id & 7;            // A: 128 rows x 8 float4
            pa[p] = *(const float4*)(Ag + (size_t)m * Cc + kk + kq * 4);
            int kb = id >> 5, nq = id & 31;           // B: 32 rows x 32 float4
            pb[p] = *(const float4*)(Bg + (size_t)(kk + kb) * Nn + nq * 4);
        }
    };

    auto storeS = [&](int buf) {
        __half* aH = smh + buf * STAGEH;
        __half* aL = aH + ASZH;
        __half* bH = aL + ASZH;
        __half* bL = bH + BSZH;
        #pragma unroll
        for (int p = 0; p < 4; p++) {
            int id = tid + p * 256;
            int m  = id >> 3, kq = id & 7;
            const float* av = (const float*)&pa[p];
            __half h0, l0, h1, l1;
            split_h(av[0], h0, l0); split_h(av[1], h1, l1);
            *(half2*)(aH + m * PAH + kq * 4)     = __halves2half2(h0, h1);
            *(half2*)(aL + m * PAH + kq * 4)     = __halves2half2(l0, l1);
            split_h(av[2], h0, l0); split_h(av[3], h1, l1);
            *(half2*)(aH + m * PAH + kq * 4 + 2) = __halves2half2(h0, h1);
            *(half2*)(aL + m * PAH + kq * 4 + 2) = __halves2half2(l0, l1);

            int kb = id >> 5, nq = id & 31;
            const float* bv = (const float*)&pb[p];
            split_h(bv[0], h0, l0); split_h(bv[1], h1, l1);
            *(half2*)(bH + kb * PBH + nq * 4)     = __halves2half2(h0, h1);
            *(half2*)(bL + kb * PBH + nq * 4)     = __halves2half2(l0, l1);
            split_h(bv[2], h0, l0); split_h(bv[3], h1, l1);
            *(half2*)(bH + kb * PBH + nq * 4 + 2) = __halves2half2(h0, h1);
            *(half2*)(bL + kb * PBH + nq * 4 + 2) = __halves2half2(l0, l1);
        }
    };

    const int lr  = lane & 15;          // fragment row
    const int lc  = (lane >> 4) & 1;    // fragment k/n half

    auto compute = [&](int buf) {
        const uint32_t aHb = sb + (uint32_t)buf * STAGEH * 2;
        const uint32_t aLb = aHb + ASZH * 2;
        const uint32_t bHb = aLb + ASZH * 2;
        const uint32_t bLb = bHb + BSZH * 2;
        #pragma unroll
        for (int ks = 0; ks < 2; ks++) {
            uint32_t bh[2][4], bl[2][4];
            #pragma unroll
            for (int fnp = 0; fnp < 2; fnp++) {
                uint32_t off = (uint32_t)(ks * 16 + lr) * (PBH * 2)
                             + (uint32_t)(wn + fnp * 16 + lc * 8) * 2;
                LDM_X4_T(bh[fnp], bHb + off);
                LDM_X4_T(bl[fnp], bLb + off);
            }
            #pragma unroll
            for (int fm = 0; fm < 4; fm++) {
                uint32_t off = (uint32_t)(wm + fm * 16 + lr) * (PAH * 2)
                             + (uint32_t)(ks * 32 + lc * 16);
                uint32_t ah[4], al[4];
                LDM_X4(ah, aHb + off);
                LDM_X4(al, aLb + off);
                #pragma unroll
                for (int fn = 0; fn < 4; fn++) {
                    const uint32_t* bph = &bh[fn >> 1][(fn & 1) * 2];
                    const uint32_t* bpl = &bl[fn >> 1][(fn & 1) * 2];
                    mma16(acc[fm][fn], ah, bph);
                    mma16(acc[fm][fn], ah, bpl);
                    mma16(acc[fm][fn], al, bph);
                }
            }
        }
    };

    loadG(0);
    storeS(0);
    __syncthreads();
    #pragma unroll 1
    for (int s = 0; s < 8; s++) {
        if (s < 7) loadG(s + 1);
        compute(s & 1);
        if (s < 7) {
            __syncthreads();
            storeS((s + 1) & 1);
            __syncthreads();
        }
    }

    #pragma unroll
    for (int fm = 0; fm < 4; fm++) {
        int row = mBlk + wm + fm * 16 + (lane >> 2);
        float b0 = bias ? bias[row]     : 0.f;
        float b8 = bias ? bias[row + 8] : 0.f;
        #pragma unroll
        for (int fn = 0; fn < 4; fn++) {
            int col = nBlk + wn + fn * 8 + (lane & 3) * 2;
            float2 v0 = { acc[fm][fn][0] + b0, acc[fm][fn][1] + b0 };
            float2 v1 = { acc[fm][fn][2] + b8, acc[fm][fn][3] + b8 };
            *(float2*)&Cg[(size_t)row * Nn + col]       = v0;
            *(float2*)&Cg[(size_t)(row + 8) * Nn + col] = v1;
        }
    }
}

// ===========================================================================
// Context partials on tensor cores: ctxp[bh][p][d][e] = sum_n k[d,n]*v[e,n]
// Per CTA: M=64(d) x N=64(e) x K=512(n), slices of 128. 4 warps = 2m x 2n.
// K[d][n] and V[e][n] are both k(n)-major => plain ldmatrix, no transpose.
// ===========================================================================
#define PKH 136                           // pitch (fp16) for 128-wide tiles
#define CTILE (64 * PKH)                  // 8704 fp16 per buffer
#define CTX_SMEM_BYTES (4 * CTILE * 2)    // 69632 B (KH, KL, VH, VL)

__global__ void __launch_bounds__(128, 1)
context_part()
{
    extern __shared__ __half smh[];
    const uint32_t sb = smem_u32(smh);
    int bh = blockIdx.x;
    int p  = blockIdx.y;
    int b = bh >> 2, h = bh & 3;
    const float* Kp = g_qkv + ((size_t)b * O3 + HID     + h * Dd) * Nn;
    const float* Vp = g_qkv + ((size_t)b * O3 + 2 * HID + h * Dd) * Nn;

    __half* kH = smh;
    __half* kL = kH + CTILE;
    __half* vH = kL + CTILE;
    __half* vL = vH + CTILE;

    const int tid  = threadIdx.x;
    const int wid  = tid >> 5;
    const int lane = tid & 31;
    const int wm = (wid >> 1) * 32;   // d offset
    const int wn = (wid & 1) * 32;    // e offset

    float acc[2][4][4];
    #pragma unroll
    for (int i = 0; i < 2; i++)
        #pragma unroll
        for (int j = 0; j < 4; j++)
            #pragma unroll
            for (int r = 0; r < 4; r++) acc[i][j][r] = 0.f;

    const int lr = lane & 15;
    const int lc = (lane >> 4) & 1;
    const uint32_t kHb = sb;
    const uint32_t kLb = kHb + CTILE * 2;
    const uint32_t vHb = kLb + CTILE * 2;
    const uint32_t vLb = vHb + CTILE * 2;

    #pragma unroll 1
    for (int sl = 0; sl < 4; sl++) {
        const int nn = p * 512 + sl * 128;
        __syncthreads();   // previous compute done before overwrite
        #pragma unroll
        for (int q = 0; q < 16; q++) {
            int id = tid + q * 128;
            int row = id >> 5, c4 = id & 31;        // 64 rows x 32 float4
            float4 kv = *(const float4*)(Kp + (size_t)row * Nn + nn + c4 * 4);
            float4 vv = *(const float4*)(Vp + (size_t)row * Nn + nn + c4 * 4);
            __half h0, l0, h1, l1;
            split_h(kv.x, h0, l0); split_h(kv.y, h1, l1);
            *(half2*)(kH + row * PKH + c4 * 4)     = __halves2half2(h0, h1);
            *(half2*)(kL + row * PKH + c4 * 4)     = __halves2half2(l0, l1);
            split_h(kv.z, h0, l0); split_h(kv.w, h1, l1);
            *(half2*)(kH + row * PKH + c4 * 4 + 2) = __halves2half2(h0, h1);
            *(half2*)(kL + row * PKH + c4 * 4 + 2) = __halves2half2(l0, l1);
            split_h(vv.x, h0, l0); split_h(vv.y, h1, l1);
            *(half2*)(vH + row * PKH + c4 * 4)     = __halves2half2(h0, h1);
            *(half2*)(vL + row * PKH + c4 * 4)     = __halves2half2(l0, l1);
            split_h(vv.z, h0, l0); split_h(vv.w, h1, l1);
            *(half2*)(vH + row * PKH + c4 * 4 + 2) = __halves2half2(h0, h1);
            *(half2*)(vL + row * PKH + c4 * 4 + 2) = __halves2half2(l0, l1);
        }
        __syncthreads();

        #pragma unroll
        for (int ks = 0; ks < 8; ks++) {
            // V fragments (B): rows = e, plain ldmatrix
            uint32_t bhf[2][4], blf[2][4];
            #pragma unroll
            for (int fnp = 0; fnp < 2; fnp++) {
                uint32_t off = (uint32_t)(wn + fnp * 16 + lc * 8 + (lane & 7)) * (PKH * 2)
                             + (uint32_t)(ks * 32 + ((lane >> 3) & 1) * 16);
                LDM_X4(bhf[fnp], vHb + off);
                LDM_X4(blf[fnp], vLb + off);
            }
            #pragma unroll
            for (int fm = 0; fm < 2; fm++) {
                uint32_t off = (uint32_t)(wm + fm * 16 + lr) * (PKH * 2)
                             + (uint32_t)(ks * 32 + lc * 16);
                uint32_t ah[4], al[4];
                LDM_X4(ah, kHb + off);
                LDM_X4(al, kLb + off);
                #pragma unroll
                for (int fn = 0; fn < 4; fn++) {
                    const uint32_t* bph = &bhf[fn >> 1][(fn & 1) * 2];
                    const uint32_t* bpl = &blf[fn >> 1][(fn & 1) * 2];
                    mma16(acc[fm][fn], ah, bph);
                    mma16(acc[fm][fn], ah, bpl);
                    mma16(acc[fm][fn], al, bph);
                }
            }
        }
    }

    float* dst = g_ctxp + ((size_t)bh * 8 + p) * (Dd * Dd);
    #pragma unroll
    for (int fm = 0; fm < 2; fm++) {
        int d0 = wm + fm * 16 + (lane >> 2);
        #pragma unroll
        for (int fn = 0; fn < 4; fn++) {
            int e0 = wn + fn * 8 + (lane & 3) * 2;
            dst[d0 * Dd + e0]           = acc[fm][fn][0];
            dst[d0 * Dd + e0 + 1]       = acc[fm][fn][1];
            dst[(d0 + 8) * Dd + e0]     = acc[fm][fn][2];
            dst[(d0 + 8) * Dd + e0 + 1] = acc[fm][fn][3];
        }
    }
}

// ===========================================================================
// Softmax over d on q (x SCALE). One thread per (b,h,n).
// ===========================================================================
__global__ void softmax_q_kernel()
{
    int idx = blockIdx.x * blockDim.x + threadIdx.x;
    if (idx >= Bn * Hh * Nn) return;
    int n = idx & (Nn - 1);
    int h = (idx >> 12) & (Hh - 1);
    int b = idx >> 14;
    float* base = g_qkv + ((size_t)b * O3 + h * Dd) * Nn + n;

    float vals[Dd];
    float mx = -INFINITY;
    #pragma unroll
    for (int d = 0; d < Dd; d++) { vals[d] = base[(size_t)d * Nn]; mx = fmaxf(mx, vals[d]); }
    float s = 0.f;
    #pragma unroll
    for (int d = 0; d < Dd; d++) { vals[d] = expf(vals[d] - mx); s += vals[d]; }
    float inv = SCALE / s;
    #pragma unroll
    for (int d = 0; d < Dd; d++) base[(size_t)d * Nn] = vals[d] * inv;
}

// ===========================================================================
// Softmax over n on k. One block per (b,h,d) row.
// ===========================================================================
__global__ void softmax_k_kernel()
{
    int row = blockIdx.x;
    int b = row >> 8;
    int hd = row & 255;
    float* base = g_qkv + ((size_t)b * O3 + HID + hd) * Nn;

    __shared__ float red[256];
    const int tid = threadIdx.x;
    float v[16];
    float mx = -INFINITY;
    #pragma unroll
    for (int i = 0; i < 16; i++) { v[i] = base[tid + i * 256]; mx = fmaxf(mx, v[i]); }
    red[tid] = mx; __syncthreads();
    for (int s = 128; s > 0; s >>= 1) { if (tid < s) red[tid] = fmaxf(red[tid], red[tid + s]); __syncthreads(); }
    mx = red[0]; __syncthreads();
    float sum = 0.f;
    #pragma unroll
    for (int i = 0; i < 16; i++) { v[i] = expf(v[i] - mx); sum += v[i]; }
    red[tid] = sum; __syncthreads();
    for (int s = 128; s > 0; s >>= 1) { if (tid < s) red[tid] += red[tid + s]; __syncthreads(); }
    float inv = 1.f / red[0];
    #pragma unroll
    for (int i = 0; i < 16; i++) base[tid + i * 256] = v[i] * inv;
}

// ===========================================================================
// W2[b][c][h*64+d] = sum_e w_out[c][h*64+e] * ctx[bh][d][e]
// ===========================================================================
__global__ void w2_kernel(const float* __restrict__ w_out)
{
    int bh = blockIdx.x;
    int b = bh >> 2, h = bh & 3;
    __shared__ float ctx[Dd * Dd];
    const int tid = threadIdx.x;

    for (int i = tid; i < Dd * Dd; i += 256) {
        float s = 0.f;
        #pragma unroll
        for (int p = 0; p < 8; p++)
            s += g_ctxp[((size_t)bh * 8 + p) * (Dd * Dd) + i];
        ctx[i] = s;
    }
    __syncthreads();

    int c = tid;
    float w[Dd];
    #pragma unroll
    for (int e = 0; e < Dd; e++) w[e] = w_out[c * HID + h * Dd + e];
    #pragma unroll 4
    for (int d = 0; d < Dd; d++) {
        float s = 0.f;
        #pragma unroll
        for (int e = 0; e < Dd; e++) s = fmaf(w[e], ctx[d * Dd + e], s);
        g_w2[((size_t)b * HID + c) * HID + h * Dd + d] = s;
    }
}

// ===========================================================================
extern "C" void kernel_launch(void* const* d_in, const int* in_sizes, int n_in,
                              void* d_out, int out_size)
{
    const float* x     = (const float*)d_in[0];
    const float* w_qkv = (const float*)d_in[1];
    const float* w_out = (const float*)d_in[2];
    const float* b_out = (const float*)d_in[3];
    float* out = (float*)d_out;

    float* qkv; cudaGetSymbolAddress((void**)&qkv, g_qkv);
    float* w2;  cudaGetSymbolAddress((void**)&w2, g_w2);

    static int attr_done = 0;
    if (!attr_done) {
        cudaFuncSetAttribute(gemm_tc, cudaFuncAttributeMaxDynamicSharedMemorySize, GT_SMEM_BYTES);
        cudaFuncSetAttribute(context_part, cudaFuncAttributeMaxDynamicSharedMemorySize, CTX_SMEM_BYTES);
        attr_done = 1;
    }

    // 1) QKV projection: [768,256] x [256,4096] per batch (fp16 3-term MMA)
    {
        dim3 grid(Nn / 128, O3 / 128, Bn);
        gemm_tc<<<grid, 256, GT_SMEM_BYTES>>>(w_qkv, 0,
                                              x, (size_t)Cc * Nn,
                                              qkv, (size_t)O3 * Nn, nullptr);
    }
    // 2) softmaxes
    softmax_q_kernel<<<(Bn * Hh * Nn) / 256, 256>>>();
    softmax_k_kernel<<<Bn * Hh * Dd, 256>>>();
    // 3) context partials over 8 n-chunks (tensor cores)
    {
        dim3 grid(Bn * Hh, 8);
        context_part<<<grid, 128, CTX_SMEM_BYTES>>>();
    }
    // 4) W2 = w_out_h @ ctx_h^T (reduces partials)
    w2_kernel<<<Bn * Hh, 256>>>(w_out);
    // 5) out = W2_b @ q_sm_b + bias: [256,256] x [256,4096] per batch
    {
        dim3 grid(Nn / 128, HID / 128, Bn);
        gemm_tc<<<grid, 256, GT_SMEM_BYTES>>>(w2, (size_t)HID * HID,
                                              qkv, (size_t)O3 * Nn,
                                              out, (size_t)HID * Nn, b_out);
    }
}